// round 15
// baseline (speedup 1.0000x reference)
#include <cuda_runtime.h>
#include <cstdint>

#define BATCH    16384
#define NFIELDS  50
#define DIM      64
#define L1DIM    128
#define L2DIM    64
#define ROWS     8       // batch rows per block
#define THREADS  64      // 2 warps, 4 rows per warp -> 16 blocks/SM at 64 regs

// dynamic shared layout (floats):
//   sFM   : ROWS*64   (reused as sH2 after h1 is computed)
//   sH1   : ROWS*128
//   sB1   : 128
//   sB2   : 64
//   sWp   : 64
//   sBias : ROWS
#define SMEM_FLOATS (ROWS*64 + ROWS*128 + 128 + 64 + 64 + ROWS)

__global__ __launch_bounds__(THREADS, 16)
void nfm_fused_kernel(const int*   __restrict__ features,
                      const float* __restrict__ emb,
                      const float* __restrict__ bias_table,
                      const float* __restrict__ w_bias,
                      const float* __restrict__ W1,
                      const float* __restrict__ b1,
                      const float* __restrict__ W2,
                      const float* __restrict__ b2,
                      const float* __restrict__ Wp,
                      const float* __restrict__ bp,
                      float*       __restrict__ out)
{
    extern __shared__ float sm[];
    float* sFM   = sm;                    // ROWS*64, reused as sH2
    float* sH1   = sFM  + ROWS*64;        // ROWS*128
    float* sB1   = sH1  + ROWS*128;       // 128
    float* sB2   = sB1  + 128;            // 64
    float* sWp   = sB2  + 64;             // 64
    float* sBias = sWp  + 64;             // ROWS
    float* sH2   = sFM;                   // overlay

    const int tid  = threadIdx.x;
    const int lane = tid & 31;
    const int wid  = tid >> 5;            // 0..1

    // ---- stage small params into shared (64 threads, 2 each for b1) --------
    sB1[tid]      = b1[tid];
    sB1[tid + 64] = b1[tid + 64];
    sB2[tid]      = b2[tid];
    sWp[tid]      = Wp[tid];

    // ---- gather + FM bi-interaction -----------------------------------------
    // warp w owns rows 4w..4w+3 as two pairs. Within a pair: lanes 0-15 = row A,
    // lanes 16-31 = row B, each lane holds 4 dims (float4) -> ONE LDG.128 per
    // field serves both rows. Indices loaded uniformly (int2-vectorized, no
    // shfl in the address path) -> all embedding LDGs independent.
    const int row0 = blockIdx.x * ROWS;
    const int half = lane >> 4;          // 0 -> row A, 1 -> row B
    const int l16  = lane & 15;

    #pragma unroll
    for (int p = 0; p < 2; ++p) {
        const int rA = wid * 4 + p * 2;
        const int rB = rA + 1;
        const int2* frA = reinterpret_cast<const int2*>(
                              features + (long)(row0 + rA) * NFIELDS);
        const int2* frB = reinterpret_cast<const int2*>(
                              features + (long)(row0 + rB) * NFIELDS);

        float4 s  = make_float4(0.f, 0.f, 0.f, 0.f);
        float4 sq = make_float4(0.f, 0.f, 0.f, 0.f);
        float  bsA = 0.f, bsB = 0.f;

        #pragma unroll
        for (int f2 = 0; f2 < NFIELDS / 2; ++f2) {        // 25 int2 per row
            const int2 ia2 = __ldg(frA + f2);             // uniform
            const int2 ib2 = __ldg(frB + f2);             // uniform
            {
                const int idx = half ? ib2.x : ia2.x;
                const float4 v = *reinterpret_cast<const float4*>(
                                     emb + (long)idx * DIM + l16 * 4);
                bsA += __ldg(bias_table + ia2.x);
                bsB += __ldg(bias_table + ib2.x);
                s.x  += v.x;       s.y  += v.y;       s.z  += v.z;       s.w  += v.w;
                sq.x += v.x * v.x; sq.y += v.y * v.y; sq.z += v.z * v.z; sq.w += v.w * v.w;
            }
            {
                const int idx = half ? ib2.y : ia2.y;
                const float4 v = *reinterpret_cast<const float4*>(
                                     emb + (long)idx * DIM + l16 * 4);
                bsA += __ldg(bias_table + ia2.y);
                bsB += __ldg(bias_table + ib2.y);
                s.x  += v.x;       s.y  += v.y;       s.z  += v.z;       s.w  += v.w;
                sq.x += v.x * v.x; sq.y += v.y * v.y; sq.z += v.z * v.z; sq.w += v.w * v.w;
            }
        }
        float4 fm;
        fm.x = 0.5f * (s.x * s.x - sq.x);
        fm.y = 0.5f * (s.y * s.y - sq.y);
        fm.z = 0.5f * (s.z * s.z - sq.z);
        fm.w = 0.5f * (s.w * s.w - sq.w);
        const int rl = half ? rB : rA;
        *reinterpret_cast<float4*>(sFM + rl * DIM + l16 * 4) = fm;
        if (lane == 0) { sBias[rA] = bsA; sBias[rB] = bsB; }
    }
    __syncthreads();

    // ---- h1 = relu(FM @ W1 + b1)  [ROWS x 128], 4 rows/warp, float4 weights -
    {
        const int c4 = lane * 4;   // thread owns cols c4..c4+3
        const int r0 = wid * 4;    // 4 rows per warp
        float acc[4][4];
        #pragma unroll
        for (int i = 0; i < 4; ++i)
            #pragma unroll
            for (int k = 0; k < 4; ++k) acc[i][k] = sB1[c4 + k];

        #pragma unroll
        for (int d = 0; d < DIM; ++d) {
            const float4 w = __ldg(reinterpret_cast<const float4*>(
                                       W1 + d * L1DIM + c4));
            #pragma unroll
            for (int i = 0; i < 4; ++i) {
                const float fv = sFM[(r0 + i) * DIM + d];   // broadcast
                acc[i][0] += fv * w.x;  acc[i][1] += fv * w.y;
                acc[i][2] += fv * w.z;  acc[i][3] += fv * w.w;
            }
        }
        #pragma unroll
        for (int i = 0; i < 4; ++i) {
            float4 r;
            r.x = fmaxf(acc[i][0], 0.f);
            r.y = fmaxf(acc[i][1], 0.f);
            r.z = fmaxf(acc[i][2], 0.f);
            r.w = fmaxf(acc[i][3], 0.f);
            *reinterpret_cast<float4*>(sH1 + (r0 + i) * L1DIM + c4) = r;
        }
    }
    __syncthreads();   // sFM dead from here; safe to overlay sH2

    // ---- h2 = relu(H1 @ W2 + b2)  [ROWS x 64], 4 rows/warp, float2 weights --
    {
        const int c2 = lane * 2;   // thread owns cols c2, c2+1
        const int r0 = wid * 4;
        float acc[4][2];
        #pragma unroll
        for (int i = 0; i < 4; ++i) {
            acc[i][0] = sB2[c2];
            acc[i][1] = sB2[c2 + 1];
        }
        #pragma unroll
        for (int d = 0; d < L1DIM; ++d) {
            const float2 w = __ldg(reinterpret_cast<const float2*>(
                                       W2 + d * L2DIM + c2));
            #pragma unroll
            for (int i = 0; i < 4; ++i) {
                const float h = sH1[(r0 + i) * L1DIM + d];  // broadcast
                acc[i][0] += h * w.x;
                acc[i][1] += h * w.y;
            }
        }
        #pragma unroll
        for (int i = 0; i < 4; ++i) {
            float2 r;
            r.x = fmaxf(acc[i][0], 0.f);
            r.y = fmaxf(acc[i][1], 0.f);
            *reinterpret_cast<float2*>(sH2 + (r0 + i) * L2DIM + c2) = r;
        }
    }
    __syncthreads();

    // ---- pred = H2 @ Wp + bp, final sum ------------------------------------
    {
        const float gb  = __ldg(w_bias);
        const float bpv = __ldg(bp);
        #pragma unroll
        for (int i = 0; i < 4; ++i) {
            const int rl = wid * 4 + i;
            float v = sH2[rl * L2DIM + lane]      * sWp[lane]
                    + sH2[rl * L2DIM + lane + 32] * sWp[lane + 32];
            #pragma unroll
            for (int o = 16; o; o >>= 1) v += __shfl_down_sync(0xffffffffu, v, o);
            if (lane == 0) out[row0 + rl] = v + bpv + sBias[rl] + gb;
        }
    }
}

extern "C" void kernel_launch(void* const* d_in, const int* in_sizes, int n_in,
                              void* d_out, int out_size)
{
    const int*   features   = (const int*)  d_in[0];
    // d_in[1] = labels (unused, shape-only in reference)
    const float* emb        = (const float*)d_in[2];
    const float* bias_table = (const float*)d_in[3];
    const float* w_bias     = (const float*)d_in[4];
    const float* W1         = (const float*)d_in[5];
    const float* b1         = (const float*)d_in[6];
    const float* W2         = (const float*)d_in[7];
    const float* b2         = (const float*)d_in[8];
    const float* Wp         = (const float*)d_in[9];
    const float* bp         = (const float*)d_in[10];
    float*       out        = (float*)d_out;

    const int smem_bytes = SMEM_FLOATS * sizeof(float);   // ~7.2 KB
    cudaFuncSetAttribute(nfm_fused_kernel,
                         cudaFuncAttributeMaxDynamicSharedMemorySize, smem_bytes);

    nfm_fused_kernel<<<BATCH / ROWS, THREADS, smem_bytes>>>(
        features, emb, bias_table, w_bias, W1, b1, W2, b2, Wp, bp, out);
}